// round 4
// baseline (speedup 1.0000x reference)
#include <cuda_runtime.h>
#include <cstdint>

#define DIM 256
#define OUT 8
#define CHUNK 16          // dims per pipeline chunk (64B per token per chunk)
#define NCHUNK 16         // DIM / CHUNK
#define ROWF 20           // floats per row in smem tile (16 + 4 pad -> conflict-free LDS.128)
#define TPG 64            // tokens per warp-group (2 per lane)
#define WARPS 8           // warps per block

// smem: per-warp double-buffered x tiles [WARPS][2][TPG*ROWF] + packed W1 + epilogue params
#define XBUF_FLOATS (WARPS * 2 * TPG * ROWF)
#define XBUF_BYTES  (XBUF_FLOATS * 4)
#define WP_BYTES    (DIM / 2 * OUT * 8)
#define SMEM_TOTAL  (XBUF_BYTES + WP_BYTES + 96 * 4)

__device__ __forceinline__ unsigned long long pk2(float lo, float hi) {
    unsigned long long r;
    asm("mov.b64 %0, {%1,%2};" : "=l"(r) : "f"(lo), "f"(hi));
    return r;
}
__device__ __forceinline__ unsigned long long fma2(unsigned long long a, unsigned long long b,
                                                   unsigned long long c) {
    unsigned long long d;
    asm("fma.rn.f32x2 %0, %1, %2, %3;" : "=l"(d) : "l"(a), "l"(b), "l"(c));
    return d;
}
__device__ __forceinline__ void cp16(uint32_t saddr, const float* gptr) {
    asm volatile("cp.async.cg.shared.global [%0], [%1], 16;" :: "r"(saddr), "l"(gptr));
}

struct EpiParams { const float *W2, *b1, *b2, *g, *bt; };

__device__ __forceinline__ void epilogue(const unsigned long long* acc, const EpiParams& ep,
                                         float* __restrict__ out, int tok)
{
    float gg[OUT];
    #pragma unroll
    for (int o = 0; o < OUT; o++) {
        float2 p = *(const float2*)&acc[o];
        float hv = p.x + p.y + ep.b1[o];
        gg[o] = 0.5f * hv * (1.0f + erff(hv * 0.70710678118654752440f));
    }
    float y[OUT];
    #pragma unroll
    for (int p = 0; p < OUT; p++) {
        float s = ep.b2[p];
        #pragma unroll
        for (int o = 0; o < OUT; o++) s = fmaf(ep.W2[p * 8 + o], gg[o], s);
        y[p] = s;
    }
    float mu = 0.0f;
    #pragma unroll
    for (int p = 0; p < OUT; p++) mu += y[p];
    mu *= 0.125f;
    float var = 0.0f;
    #pragma unroll
    for (int p = 0; p < OUT; p++) { float d = y[p] - mu; var = fmaf(d, d, var); }
    var *= 0.125f;
    float rs = rsqrtf(var + 1e-5f);

    float4 o0, o1;
    o0.x = (y[0] - mu) * rs * ep.g[0] + ep.bt[0];
    o0.y = (y[1] - mu) * rs * ep.g[1] + ep.bt[1];
    o0.z = (y[2] - mu) * rs * ep.g[2] + ep.bt[2];
    o0.w = (y[3] - mu) * rs * ep.g[3] + ep.bt[3];
    o1.x = (y[4] - mu) * rs * ep.g[4] + ep.bt[4];
    o1.y = (y[5] - mu) * rs * ep.g[5] + ep.bt[5];
    o1.z = (y[6] - mu) * rs * ep.g[6] + ep.bt[6];
    o1.w = (y[7] - mu) * rs * ep.g[7] + ep.bt[7];
    float4* op = (float4*)(out + (size_t)tok * 8);
    op[0] = o0;
    op[1] = o1;
}

__global__ __launch_bounds__(256, 2)
void ffn_kernel(const float* __restrict__ x, const float* __restrict__ W1,
                const float* __restrict__ b1, const float* __restrict__ W2,
                const float* __restrict__ b2, const float* __restrict__ gamma,
                const float* __restrict__ beta, float* __restrict__ out, int ntok)
{
    extern __shared__ char smem_raw[];
    float* xbuf = (float*)smem_raw;
    unsigned long long* Wp = (unsigned long long*)(smem_raw + XBUF_BYTES);
    float* tail = (float*)(smem_raw + XBUF_BYTES + WP_BYTES);
    float* sW2 = tail;          // 64
    float* sb1 = tail + 64;     // 8
    float* sb2 = tail + 72;     // 8
    float* sg  = tail + 80;     // 8
    float* sbt = tail + 88;     // 8

    const int tid = threadIdx.x;

    // ---- one-time init: packed W1 dim-pairs Wp[dp*8+o] = {W1[o][2dp], W1[o][2dp+1]} ----
    {
        int e = tid * 4;            // 256 threads x 4 = 1024 entries = 128 dp x 8 out
        #pragma unroll
        for (int q = 0; q < 4; q++) {
            int idx = e + q;
            int d = idx >> 3;
            int o = idx & 7;
            Wp[idx] = pk2(W1[o * DIM + 2 * d], W1[o * DIM + 2 * d + 1]);
        }
        if (tid < 64) sW2[tid] = W2[tid];
        if (tid < 8) { sb1[tid] = b1[tid]; sb2[tid] = b2[tid]; sg[tid] = gamma[tid]; sbt[tid] = beta[tid]; }
    }
    __syncthreads();

    const int lane = tid & 31;
    const int warp = tid >> 5;
    const int warp_global = blockIdx.x * WARPS + warp;
    const int nwarps = gridDim.x * WARPS;
    const int ngroups = (ntok + TPG - 1) / TPG;

    float* wtile = xbuf + warp * 2 * (TPG * ROWF);
    const uint32_t wtile_su = (uint32_t)__cvta_generic_to_shared(wtile);
    EpiParams ep{sW2, sb1, sb2, sg, sbt};

    // per-lane staging split: lin = it*32+lane, r = lin>>2 (token row), j = lin&3 (16B piece)
    const int r0 = lane >> 2, j0 = lane & 3;

    for (int g = warp_global; g < ngroups; g += nwarps) {
        const int base = g * TPG;
        const bool full = (base + TPG) <= ntok;
        const float* xg = x + (size_t)base * DIM;

        // ---- prefetch chunk 0 into stage 0 ----
        if (full) {
            #pragma unroll
            for (int it = 0; it < 8; it++) {
                int r = it * 8 + r0;
                cp16(wtile_su + (uint32_t)(r * ROWF + j0 * 4) * 4,
                     xg + (size_t)r * DIM + j0 * 4);
            }
        } else {
            #pragma unroll
            for (int it = 0; it < 8; it++) {
                int r = it * 8 + r0;
                if (base + r < ntok)
                    cp16(wtile_su + (uint32_t)(r * ROWF + j0 * 4) * 4,
                         xg + (size_t)r * DIM + j0 * 4);
            }
        }
        asm volatile("cp.async.commit_group;");

        unsigned long long accA[OUT], accB[OUT];
        #pragma unroll
        for (int o = 0; o < OUT; o++) { accA[o] = 0ull; accB[o] = 0ull; }

        const float* rowA_base = wtile + lane * ROWF;
        const float* rowB_base = wtile + (lane + 32) * ROWF;

        #pragma unroll
        for (int c = 0; c < NCHUNK; c++) {
            if (c + 1 < NCHUNK) {
                const int stg = (c + 1) & 1;
                const int coff = (c + 1) * CHUNK;
                if (full) {
                    #pragma unroll
                    for (int it = 0; it < 8; it++) {
                        int r = it * 8 + r0;
                        cp16(wtile_su + (uint32_t)((stg * TPG + r) * ROWF + j0 * 4) * 4,
                             xg + (size_t)r * DIM + coff + j0 * 4);
                    }
                } else {
                    #pragma unroll
                    for (int it = 0; it < 8; it++) {
                        int r = it * 8 + r0;
                        if (base + r < ntok)
                            cp16(wtile_su + (uint32_t)((stg * TPG + r) * ROWF + j0 * 4) * 4,
                                 xg + (size_t)r * DIM + coff + j0 * 4);
                    }
                }
                asm volatile("cp.async.commit_group;");
                asm volatile("cp.async.wait_group 1;");
            } else {
                asm volatile("cp.async.wait_group 0;");
            }
            __syncwarp();

            // ---- compute chunk c from stage (c&1): 2 tokens per thread ----
            const int soff = (c & 1) * (TPG * ROWF);
            const float* rA = rowA_base + soff;
            const float* rB = rowB_base + soff;
            #pragma unroll
            for (int i = 0; i < 4; i++) {
                ulonglong2 xa = *(const ulonglong2*)(rA + i * 4);
                ulonglong2 xb = *(const ulonglong2*)(rB + i * 4);
                const int dpg = c * 8 + 2 * i;
                const ulonglong2* w = (const ulonglong2*)(Wp + dpg * OUT);
                ulonglong2 w0 = w[0], w1 = w[1], w2 = w[2], w3 = w[3];
                accA[0] = fma2(xa.x, w0.x, accA[0]);  accB[0] = fma2(xb.x, w0.x, accB[0]);
                accA[1] = fma2(xa.x, w0.y, accA[1]);  accB[1] = fma2(xb.x, w0.y, accB[1]);
                accA[2] = fma2(xa.x, w1.x, accA[2]);  accB[2] = fma2(xb.x, w1.x, accB[2]);
                accA[3] = fma2(xa.x, w1.y, accA[3]);  accB[3] = fma2(xb.x, w1.y, accB[3]);
                accA[4] = fma2(xa.x, w2.x, accA[4]);  accB[4] = fma2(xb.x, w2.x, accB[4]);
                accA[5] = fma2(xa.x, w2.y, accA[5]);  accB[5] = fma2(xb.x, w2.y, accB[5]);
                accA[6] = fma2(xa.x, w3.x, accA[6]);  accB[6] = fma2(xb.x, w3.x, accB[6]);
                accA[7] = fma2(xa.x, w3.y, accA[7]);  accB[7] = fma2(xb.x, w3.y, accB[7]);
                ulonglong2 w4 = w[4], w5 = w[5], w6 = w[6], w7 = w[7];
                accA[0] = fma2(xa.y, w4.x, accA[0]);  accB[0] = fma2(xb.y, w4.x, accB[0]);
                accA[1] = fma2(xa.y, w4.y, accA[1]);  accB[1] = fma2(xb.y, w4.y, accB[1]);
                accA[2] = fma2(xa.y, w5.x, accA[2]);  accB[2] = fma2(xb.y, w5.x, accB[2]);
                accA[3] = fma2(xa.y, w5.y, accA[3]);  accB[3] = fma2(xb.y, w5.y, accB[3]);
                accA[4] = fma2(xa.y, w6.x, accA[4]);  accB[4] = fma2(xb.y, w6.x, accB[4]);
                accA[5] = fma2(xa.y, w6.y, accA[5]);  accB[5] = fma2(xb.y, w6.y, accB[5]);
                accA[6] = fma2(xa.y, w7.x, accA[6]);  accB[6] = fma2(xb.y, w7.x, accB[6]);
                accA[7] = fma2(xa.y, w7.y, accA[7]);  accB[7] = fma2(xb.y, w7.y, accB[7]);
            }
            __syncwarp();
        }

        // ---- epilogue: this thread owns tokens base+lane and base+32+lane ----
        const int tokA = base + lane;
        const int tokB = base + 32 + lane;
        if (tokA < ntok) epilogue(accA, ep, out, tokA);
        if (tokB < ntok) epilogue(accB, ep, out, tokB);
        __syncwarp();   // protect tile reuse across group iterations
    }
}

extern "C" void kernel_launch(void* const* d_in, const int* in_sizes, int n_in,
                              void* d_out, int out_size)
{
    const float* x     = (const float*)d_in[0];
    const float* W1    = (const float*)d_in[1];
    const float* b1    = (const float*)d_in[2];
    const float* W2    = (const float*)d_in[3];
    const float* b2    = (const float*)d_in[4];
    const float* gamma = (const float*)d_in[5];
    const float* beta  = (const float*)d_in[6];
    float* out = (float*)d_out;

    int ntok = in_sizes[0] / DIM;               // 262144 for the bench shape
    int ngroups = (ntok + TPG - 1) / TPG;       // warp-groups of 64 tokens
    int blocks = (ngroups + WARPS - 1) / WARPS;
    if (blocks > 1024) blocks = 1024;
    if (blocks < 1) blocks = 1;

    cudaFuncSetAttribute(ffn_kernel, cudaFuncAttributeMaxDynamicSharedMemorySize, SMEM_TOTAL);
    ffn_kernel<<<blocks, 256, SMEM_TOTAL>>>(x, W1, b1, W2, b2, gamma, beta, out, ntok);
}